// round 1
// baseline (speedup 1.0000x reference)
#include <cuda_runtime.h>

// SSIM loss, separable 11-tap Gaussian, fused single pass.
// pred = d_in[0], gt = d_in[1], fp32 [16,3,512,512]; out = scalar fp32.

static constexpr int Hdim = 512;
static constexpr int Wdim = 512;
static constexpr int TX   = 128;   // threads per block == columns per tile
static constexpr int RPB  = 64;    // output rows per block
static constexpr int NCHUNK = 7;   // ceil((RPB+10)/11) chunks of 11 input rows

__device__ double g_accum;

__global__ void ssim_zero_kernel() { g_accum = 0.0; }

__global__ void __launch_bounds__(TX, 4) ssim_main_kernel(
    const float* __restrict__ Pg, const float* __restrict__ Gg)
{
    // 11-tap normalized gaussian (sigma=1.5), compile-time constants so ptxas
    // emits FFMA with immediate multiplier (rt_SMSP=1 on sm_103a).
    static constexpr float WG[11] = {
        0.00102840f, 0.00759880f, 0.03600080f, 0.10936070f, 0.21300550f,
        0.26601190f, 0.21300550f, 0.10936070f, 0.03600080f, 0.00759880f,
        0.00102840f };
    static constexpr float C1c = 1.0e-4f;   // 0.01^2
    static constexpr float C2c = 9.0e-4f;   // 0.03^2

    __shared__ float2 sm[11][TX + 16];      // (pred, gt) pairs, 11-row chunk + halo
    __shared__ float ws[TX / 32];

    const int t  = threadIdx.x;
    const int x0 = blockIdx.x * TX;
    const int y0 = blockIdx.y * RPB;
    const long poff = (long)blockIdx.z * (Hdim * Wdim);
    const float* __restrict__ p = Pg + poff;
    const float* __restrict__ g = Gg + poff;

    // register ring: horizontally-convolved rows for 5 fields
    float rm1[11], rm2[11], rs1[11], rs2[11], rsx[11];
    float acc = 0.f;

    for (int chunk = 0; chunk < NCHUNK; ++chunk) {
        const int base = y0 - 5 + chunk * 11;  // first input row of this chunk

        __syncthreads();   // previous chunk's smem reads complete
        // cooperative load of 11 rows x 138 cols of (p,g) pairs, zero-padded
        for (int idx = t; idx < 11 * 138; idx += TX) {
            int rr = idx / 138;
            int c  = idx - rr * 138;
            int gy = base + rr;
            int gx = x0 - 5 + c;
            float pv = 0.f, gv = 0.f;
            if ((unsigned)gy < (unsigned)Hdim && (unsigned)gx < (unsigned)Wdim) {
                int o = gy * Wdim + gx;
                pv = p[o];
                gv = g[o];
            }
            sm[rr][c] = make_float2(pv, gv);
        }
        __syncthreads();

        #pragma unroll
        for (int rr = 0; rr < 11; ++rr) {
            // horizontal 11-tap conv for this thread's column, 5 fields
            float hm1 = 0.f, hm2 = 0.f, hs1 = 0.f, hs2 = 0.f, hsx = 0.f;
            #pragma unroll
            for (int k = 0; k < 11; ++k) {
                float2 v = sm[rr][t + k];
                float w = WG[k];
                hm1 += w * v.x;
                hm2 += w * v.y;
                hs1 += w * (v.x * v.x);
                hs2 += w * (v.y * v.y);
                hsx += w * (v.x * v.y);
            }
            rm1[rr] = hm1; rm2[rr] = hm2;
            rs1[rr] = hs1; rs2[rr] = hs2; rsx[rr] = hsx;

            // chunk stride == ring depth (11): row (chunk*11+rr) lives in slot rr,
            // so all ring indices below are compile-time after unrolling.
            const int cr = chunk * 11 + rr;     // row index rel. to (y0-5)
            if (cr >= 10 && cr <= RPB + 9) {    // output row yo = y0 + cr - 10
                float m1 = 0.f, m2 = 0.f, s1 = 0.f, s2 = 0.f, sx = 0.f;
                #pragma unroll
                for (int j = 0; j < 11; ++j) {
                    const int sl = (rr + 1 + j) % 11;  // slot of row (cr-10+j)
                    float w = WG[j];
                    m1 += w * rm1[sl];
                    m2 += w * rm2[sl];
                    s1 += w * rs1[sl];
                    s2 += w * rs2[sl];
                    sx += w * rsx[sl];
                }
                float mu11 = m1 * m1;
                float mu22 = m2 * m2;
                float mu12 = m1 * m2;
                float sg1  = s1 - mu11;
                float sg2  = s2 - mu22;
                float sg12 = sx - mu12;
                float num = (2.f * mu12 + C1c) * (2.f * sg12 + C2c);
                float den = (mu11 + mu22 + C1c) * (sg1 + sg2 + C2c);
                acc += __fdividef(num, den);
            }
        }
    }

    // block reduction -> one double atomic per block
    #pragma unroll
    for (int off = 16; off > 0; off >>= 1)
        acc += __shfl_down_sync(0xFFFFFFFFu, acc, off);
    if ((t & 31) == 0) ws[t >> 5] = acc;
    __syncthreads();
    if (t == 0) {
        float s = 0.f;
        #pragma unroll
        for (int i = 0; i < TX / 32; ++i) s += ws[i];
        atomicAdd(&g_accum, (double)s);
    }
}

__global__ void ssim_final_kernel(float* out, double invN) {
    out[0] = (float)(1.0 - g_accum * invN);
}

extern "C" void kernel_launch(void* const* d_in, const int* in_sizes, int n_in,
                              void* d_out, int out_size)
{
    const float* pred = (const float*)d_in[0];
    const float* gt   = (const float*)d_in[1];
    const long total  = (long)in_sizes[0];           // B*C*H*W elements
    const int planes  = (int)(total / (Hdim * Wdim)); // B*C

    ssim_zero_kernel<<<1, 1>>>();
    dim3 grid(Wdim / TX, Hdim / RPB, planes);
    ssim_main_kernel<<<grid, TX>>>(pred, gt);
    ssim_final_kernel<<<1, 1>>>((float*)d_out, 1.0 / (double)total);
}